// round 2
// baseline (speedup 1.0000x reference)
#include <cuda_runtime.h>
#include <cstdint>
#include <cstddef>

// Problem constants (fixed shapes from the reference)
#define N_SRC0   286000
#define N_DST0   11000
#define N_E0     275000
#define N_DST1   1000
#define N_E1     10000
#define F_IN     602
#define HID      256
#define NCLS     41

// ---------------- scratch (device globals; no runtime allocation) ----------
__device__ int   g_cnt0[N_DST0];
__device__ int   g_cur0[N_DST0];
__device__ int   g_off0[N_DST0 + 1];
__device__ int   g_src0[N_E0];

__device__ int   g_cnt1[N_DST1];
__device__ int   g_cur1[N_DST1];
__device__ int   g_off1[N_DST1 + 1];
__device__ int   g_src1[N_E1];

__device__ float g_hagg0[(size_t)N_DST0 * F_IN];   // ~26.5 MB
__device__ float g_h    [(size_t)N_DST0 * HID];    // ~11.3 MB
__device__ float g_hagg1[(size_t)N_DST1 * HID];    // ~1 MB

// ---------------- setup kernels --------------------------------------------
__global__ void k_zero() {
    int i = blockIdx.x * blockDim.x + threadIdx.x;
    if (i < N_DST0) { g_cnt0[i] = 0; g_cur0[i] = 0; }
    if (i < N_DST1) { g_cnt1[i] = 0; g_cur1[i] = 0; }
}

__global__ void k_count(const int* __restrict__ e0_dst,
                        const int* __restrict__ e1_dst) {
    int i = blockIdx.x * blockDim.x + threadIdx.x;
    if (i < N_E0) atomicAdd(&g_cnt0[e0_dst[i]], 1);
    if (i < N_E1) atomicAdd(&g_cnt1[e1_dst[i]], 1);
}

// single-block exclusive scan
__device__ void scan_excl(const int* cnt, int* off, int n) {
    __shared__ int sh[1024];
    __shared__ int carry;
    const int t = threadIdx.x;
    if (t == 0) carry = 0;
    __syncthreads();
    for (int base = 0; base < n; base += 1024) {
        int i = base + t;
        int v = (i < n) ? cnt[i] : 0;
        sh[t] = v;
        __syncthreads();
        #pragma unroll
        for (int s = 1; s < 1024; s <<= 1) {
            int tmp = (t >= s) ? sh[t - s] : 0;
            __syncthreads();
            sh[t] += tmp;
            __syncthreads();
        }
        if (i < n) off[i] = carry + sh[t] - v;   // exclusive
        __syncthreads();
        if (t == 0) carry += sh[1023];
        __syncthreads();
    }
    if (t == 0) off[n] = carry;
}

__global__ void k_scan() {
    if (blockIdx.x == 0) scan_excl(g_cnt0, g_off0, N_DST0);
    else                 scan_excl(g_cnt1, g_off1, N_DST1);
}

__global__ void k_scatter(const int* __restrict__ e0_src,
                          const int* __restrict__ e0_dst,
                          const int* __restrict__ e1_src,
                          const int* __restrict__ e1_dst) {
    int i = blockIdx.x * blockDim.x + threadIdx.x;
    if (i < N_E0) {
        int d = e0_dst[i];
        int p = atomicAdd(&g_cur0[d], 1);
        g_src0[g_off0[d] + p] = e0_src[i];
    }
    if (i < N_E1) {
        int d = e1_dst[i];
        int p = atomicAdd(&g_cur1[d], 1);
        g_src1[g_off1[d] + p] = e1_src[i];
    }
}

// ---------------- layer-0 mean aggregation (the big gather) ----------------
// One block per dst node, 128 threads; float2 lanes (rows are 8B aligned: 602%2==0).
#define F2 (F_IN / 2)   // 301

__global__ void k_agg0(const float* __restrict__ x) {
    const int dst = blockIdx.x;
    const int beg = g_off0[dst];
    const int end = g_off0[dst + 1];
    const int t   = threadIdx.x;

    float2 acc[3];
    acc[0] = make_float2(0.f, 0.f);
    acc[1] = make_float2(0.f, 0.f);
    acc[2] = make_float2(0.f, 0.f);

    #pragma unroll 2
    for (int e = beg; e < end; ++e) {
        const float2* row = reinterpret_cast<const float2*>(x + (size_t)g_src0[e] * F_IN);
        float2 v0 = __ldg(row + t);
        float2 v1 = __ldg(row + t + 128);
        acc[0].x += v0.x; acc[0].y += v0.y;
        acc[1].x += v1.x; acc[1].y += v1.y;
        if (t + 256 < F2) {
            float2 v2 = __ldg(row + t + 256);
            acc[2].x += v2.x; acc[2].y += v2.y;
        }
    }
    const float inv = (end > beg) ? 1.0f / (float)(end - beg) : 0.0f;
    float2* orow = reinterpret_cast<float2*>(g_hagg0 + (size_t)dst * F_IN);
    orow[t]       = make_float2(acc[0].x * inv, acc[0].y * inv);
    orow[t + 128] = make_float2(acc[1].x * inv, acc[1].y * inv);
    if (t + 256 < F2)
        orow[t + 256] = make_float2(acc[2].x * inv, acc[2].y * inv);
}

// ---------------- layer-0 GEMM: h = relu(Xd@Ws + Hagg@Wn + b0) -------------
// 128x64 tile, BK=16, 256 threads, 8x4 micro-tile, double-buffered smem,
// single flattened 76-tile pipeline spanning both input phases.
#define BM  128
#define BN  64
#define BK  16
#define KT  38           // ceil(602/16)
#define NT  (2 * KT)     // 76

__global__ __launch_bounds__(256, 2)
void k_gemm0(const float* __restrict__ x,
             const float* __restrict__ Ws,
             const float* __restrict__ Wn,
             const float* __restrict__ bias) {
    __shared__ float As[2][BK][BM + 4];
    __shared__ float Bs[2][BK][BN];

    const int tid = threadIdx.x;
    const int tx = tid & 15;          // 0..15 : col group
    const int ty = tid >> 4;          // 0..15 : row group
    const int rowBase = blockIdx.y * BM;
    const int colBase = blockIdx.x * BN;

    // prefetch indexing
    const int arow = tid >> 1;        // 0..127 : A tile row
    const int kseg = (tid & 1) * 8;   // 0 or 8 : A k segment
    const int grow = rowBase + arow;
    const int bk   = tid >> 4;        // 0..15 : B tile k
    const int bcol = (tid & 15) * 4;  // B tile col base

    float acc[8][4] = {};
    float2 aP[4];
    float4 bP;

    auto prefetch = [&](int tt) {
        const int phase = (tt >= KT);
        const int k0 = (phase ? tt - KT : tt) * BK;
        const float* A = phase ? g_hagg0 : x;
        const float* W = phase ? Wn : Ws;
        #pragma unroll
        for (int j = 0; j < 4; ++j) {
            int k = k0 + kseg + 2 * j;
            if (grow < N_DST0 && k < F_IN)
                aP[j] = *reinterpret_cast<const float2*>(A + (size_t)grow * F_IN + k);
            else
                aP[j] = make_float2(0.f, 0.f);
        }
        int k = k0 + bk;
        if (k < F_IN)
            bP = *reinterpret_cast<const float4*>(W + (size_t)k * HID + colBase + bcol);
        else
            bP = make_float4(0.f, 0.f, 0.f, 0.f);
    };
    auto store_smem = [&](int buf) {
        #pragma unroll
        for (int j = 0; j < 4; ++j) {
            As[buf][kseg + 2 * j][arow]     = aP[j].x;
            As[buf][kseg + 2 * j + 1][arow] = aP[j].y;
        }
        *reinterpret_cast<float4*>(&Bs[buf][bk][bcol]) = bP;
    };

    prefetch(0);
    store_smem(0);
    __syncthreads();

    for (int tt = 0; tt < NT; ++tt) {
        const int buf = tt & 1;
        if (tt + 1 < NT) prefetch(tt + 1);

        #pragma unroll
        for (int kk = 0; kk < BK; ++kk) {
            float4 a0 = *reinterpret_cast<const float4*>(&As[buf][kk][ty * 8]);
            float4 a1 = *reinterpret_cast<const float4*>(&As[buf][kk][ty * 8 + 4]);
            float4 b  = *reinterpret_cast<const float4*>(&Bs[buf][kk][tx * 4]);
            float av[8] = {a0.x, a0.y, a0.z, a0.w, a1.x, a1.y, a1.z, a1.w};
            float bv[4] = {b.x, b.y, b.z, b.w};
            #pragma unroll
            for (int i = 0; i < 8; ++i)
                #pragma unroll
                for (int j = 0; j < 4; ++j)
                    acc[i][j] += av[i] * bv[j];
        }

        if (tt + 1 < NT) {
            store_smem(1 - buf);
            __syncthreads();
        }
    }

    // epilogue: bias + relu, float4 stores
    float bv[4];
    #pragma unroll
    for (int j = 0; j < 4; ++j) bv[j] = bias[colBase + tx * 4 + j];

    #pragma unroll
    for (int i = 0; i < 8; ++i) {
        int r = rowBase + ty * 8 + i;
        if (r >= N_DST0) continue;
        float4 v;
        v.x = fmaxf(acc[i][0] + bv[0], 0.0f);
        v.y = fmaxf(acc[i][1] + bv[1], 0.0f);
        v.z = fmaxf(acc[i][2] + bv[2], 0.0f);
        v.w = fmaxf(acc[i][3] + bv[3], 0.0f);
        *reinterpret_cast<float4*>(g_h + (size_t)r * HID + colBase + tx * 4) = v;
    }
}

// ---------------- layer-1 mean aggregation ---------------------------------
__global__ void k_agg1() {
    const int dst = blockIdx.x;
    const int beg = g_off1[dst];
    const int end = g_off1[dst + 1];
    const int t   = threadIdx.x;     // 256 threads, one feature each

    float acc = 0.f;
    for (int e = beg; e < end; ++e)
        acc += g_h[(size_t)g_src1[e] * HID + t];

    const float inv = (end > beg) ? 1.0f / (float)(end - beg) : 0.0f;
    g_hagg1[(size_t)dst * HID + t] = acc * inv;
}

// ---------------- output layer ----------------------------------------------
__global__ void k_out(const float* __restrict__ Ws1,
                      const float* __restrict__ Wn1,
                      const float* __restrict__ b1,
                      float* __restrict__ out) {
    __shared__ float hd[HID];
    __shared__ float ha[HID];
    const int dst = blockIdx.x;
    for (int i = threadIdx.x; i < HID; i += blockDim.x) {
        hd[i] = g_h[(size_t)dst * HID + i];      // h_dst1 = h[:1000]
        ha[i] = g_hagg1[(size_t)dst * HID + i];
    }
    __syncthreads();
    const int c = threadIdx.x;
    if (c < NCLS) {
        float s = b1[c];
        #pragma unroll 4
        for (int k = 0; k < HID; ++k)
            s += hd[k] * Ws1[k * NCLS + c] + ha[k] * Wn1[k * NCLS + c];
        out[dst * NCLS + c] = s;
    }
}

// ---------------- launch ------------------------------------------------------
extern "C" void kernel_launch(void* const* d_in, const int* in_sizes, int n_in,
                              void* d_out, int out_size) {
    const float* x      = (const float*)d_in[0];
    const float* Wself0 = (const float*)d_in[1];
    const float* Wneigh0= (const float*)d_in[2];
    const float* b0     = (const float*)d_in[3];
    const float* Wself1 = (const float*)d_in[4];
    const float* Wneigh1= (const float*)d_in[5];
    const float* b1     = (const float*)d_in[6];
    const int*   e0_src = (const int*)d_in[7];
    const int*   e0_dst = (const int*)d_in[8];
    const int*   e1_src = (const int*)d_in[9];
    const int*   e1_dst = (const int*)d_in[10];
    float* out = (float*)d_out;

    k_zero   <<<(N_DST0 + 255) / 256, 256>>>();
    k_count  <<<(N_E0   + 255) / 256, 256>>>(e0_dst, e1_dst);
    k_scan   <<<2, 1024>>>();
    k_scatter<<<(N_E0   + 255) / 256, 256>>>(e0_src, e0_dst, e1_src, e1_dst);
    k_agg0   <<<N_DST0, 128>>>(x);
    k_gemm0  <<<dim3(HID / BN, (N_DST0 + BM - 1) / BM), 256>>>(x, Wself0, Wneigh0, b0);
    k_agg1   <<<N_DST1, 256>>>();
    k_out    <<<N_DST1, 64>>>(Wself1, Wneigh1, b1, out);
}

// round 4
// speedup vs baseline: 1.5109x; 1.5109x over previous
#include <cuda_runtime.h>
#include <cuda_bf16.h>
#include <cstdint>
#include <cstddef>

// Problem constants
#define N_SRC0   286000
#define N_DST0   11000
#define N_E0     275000
#define N_DST1   1000
#define N_E1     10000
#define F_IN     602
#define HID      256
#define NCLS     41
#define KPAD     640          // 20 chunks of 32
#define F2       (F_IN / 2)   // 301
#define P2       (KPAD / 2)   // 320

// ---------------- scratch (device globals; no runtime allocation) ----------
__device__ int g_cnt0[N_DST0];
__device__ int g_cur0[N_DST0];
__device__ int g_off0[N_DST0 + 1];
__device__ int g_src0[N_E0];
__device__ int g_cnt1[N_DST1];
__device__ int g_cur1[N_DST1];
__device__ int g_off1[N_DST1 + 1];
__device__ int g_src1[N_E1];

__device__ __align__(16) __nv_bfloat16 g_xhi[(size_t)N_DST0 * KPAD];
__device__ __align__(16) __nv_bfloat16 g_xlo[(size_t)N_DST0 * KPAD];
__device__ __align__(16) __nv_bfloat16 g_ahi[(size_t)N_DST0 * KPAD];
__device__ __align__(16) __nv_bfloat16 g_alo[(size_t)N_DST0 * KPAD];
__device__ __align__(16) __nv_bfloat16 g_wshi[256 * KPAD];   // [n][k]  (W^T)
__device__ __align__(16) __nv_bfloat16 g_wslo[256 * KPAD];
__device__ __align__(16) __nv_bfloat16 g_wnhi[256 * KPAD];
__device__ __align__(16) __nv_bfloat16 g_wnlo[256 * KPAD];

__device__ float g_h    [(size_t)N_DST0 * HID];
__device__ float g_hagg1[(size_t)N_DST1 * HID];

__device__ __forceinline__ void split_bf16(float v, __nv_bfloat16& h, __nv_bfloat16& l) {
    h = __float2bfloat16(v);
    l = __float2bfloat16(v - __bfloat162float(h));
}

// ---------------- CSR build --------------------------------------------------
__global__ void k_zero() {
    int i = blockIdx.x * blockDim.x + threadIdx.x;
    if (i < N_DST0) { g_cnt0[i] = 0; g_cur0[i] = 0; }
    if (i < N_DST1) { g_cnt1[i] = 0; g_cur1[i] = 0; }
}

__global__ void k_count(const int* __restrict__ e0_dst, const int* __restrict__ e1_dst) {
    int i = blockIdx.x * blockDim.x + threadIdx.x;
    if (i < N_E0) atomicAdd(&g_cnt0[e0_dst[i]], 1);
    if (i < N_E1) atomicAdd(&g_cnt1[e1_dst[i]], 1);
}

__device__ void scan_excl(const int* cnt, int* off, int n) {
    __shared__ int wsum[32];
    __shared__ int carry;
    const int t = threadIdx.x, lane = t & 31, w = t >> 5;
    if (t == 0) carry = 0;
    __syncthreads();
    for (int base = 0; base < n; base += 1024) {
        int i = base + t;
        int v = (i < n) ? cnt[i] : 0;
        int s = v;
        #pragma unroll
        for (int d = 1; d < 32; d <<= 1) { int u = __shfl_up_sync(~0u, s, d); if (lane >= d) s += u; }
        if (lane == 31) wsum[w] = s;
        __syncthreads();
        if (w == 0) {
            int ws = wsum[lane];
            #pragma unroll
            for (int d = 1; d < 32; d <<= 1) { int u = __shfl_up_sync(~0u, ws, d); if (lane >= d) ws += u; }
            wsum[lane] = ws;
        }
        __syncthreads();
        int woff = (w > 0) ? wsum[w - 1] : 0;
        if (i < n) off[i] = carry + woff + s - v;
        __syncthreads();
        if (t == 0) carry += wsum[31];
        __syncthreads();
    }
    if (threadIdx.x == 0) off[n] = carry;
}

__global__ void k_scan() {
    if (blockIdx.x == 0) scan_excl(g_cnt0, g_off0, N_DST0);
    else                 scan_excl(g_cnt1, g_off1, N_DST1);
}

__global__ void k_scatter(const int* __restrict__ e0_src, const int* __restrict__ e0_dst,
                          const int* __restrict__ e1_src, const int* __restrict__ e1_dst) {
    int i = blockIdx.x * blockDim.x + threadIdx.x;
    if (i < N_E0) {
        int d = e0_dst[i];
        int p = atomicAdd(&g_cur0[d], 1);
        g_src0[g_off0[d] + p] = e0_src[i];
    }
    if (i < N_E1) {
        int d = e1_dst[i];
        int p = atomicAdd(&g_cur1[d], 1);
        g_src1[g_off1[d] + p] = e1_src[i];
    }
}

// ---------------- bf16 hi/lo prep --------------------------------------------
__global__ void k_prep_w(const float* __restrict__ Ws, const float* __restrict__ Wn) {
    int idx = blockIdx.x * blockDim.x + threadIdx.x;
    if (idx >= 2 * 256 * KPAD) return;
    int m = idx / (256 * KPAD);
    int r = idx % (256 * KPAD);
    int n = r / KPAD;
    int k = r % KPAD;
    const float* W = m ? Wn : Ws;
    float v = (k < F_IN) ? W[(size_t)k * HID + n] : 0.0f;
    __nv_bfloat16 h, l; split_bf16(v, h, l);
    if (m) { g_wnhi[n * KPAD + k] = h; g_wnlo[n * KPAD + k] = l; }
    else   { g_wshi[n * KPAD + k] = h; g_wslo[n * KPAD + k] = l; }
}

__global__ void k_prep_x(const float* __restrict__ x) {
    int idx = blockIdx.x * blockDim.x + threadIdx.x;     // N_DST0 * P2
    if (idx >= N_DST0 * P2) return;
    int row = idx / P2;
    int p   = idx % P2;
    float2 v = make_float2(0.f, 0.f);
    if (p < F2) v = reinterpret_cast<const float2*>(x)[(size_t)row * F2 + p];
    __nv_bfloat16 hx, lx, hy, ly;
    split_bf16(v.x, hx, lx);
    split_bf16(v.y, hy, ly);
    __nv_bfloat162 hp; hp.x = hx; hp.y = hy;
    __nv_bfloat162 lp; lp.x = lx; lp.y = ly;
    reinterpret_cast<__nv_bfloat162*>(g_xhi)[(size_t)row * P2 + p] = hp;
    reinterpret_cast<__nv_bfloat162*>(g_xlo)[(size_t)row * P2 + p] = lp;
}

// ---------------- layer-0 mean aggregation (big gather) ----------------------
__global__ void k_agg0(const float* __restrict__ x) {
    const int dst = blockIdx.x;
    const int beg = g_off0[dst];
    const int end = g_off0[dst + 1];
    const int t   = threadIdx.x;

    float2 acc[3];
    acc[0] = make_float2(0.f, 0.f);
    acc[1] = make_float2(0.f, 0.f);
    acc[2] = make_float2(0.f, 0.f);

    #pragma unroll 2
    for (int e = beg; e < end; ++e) {
        const float2* row = reinterpret_cast<const float2*>(x + (size_t)g_src0[e] * F_IN);
        float2 v0 = __ldg(row + t);
        float2 v1 = __ldg(row + t + 128);
        acc[0].x += v0.x; acc[0].y += v0.y;
        acc[1].x += v1.x; acc[1].y += v1.y;
        if (t + 256 < F2) {
            float2 v2 = __ldg(row + t + 256);
            acc[2].x += v2.x; acc[2].y += v2.y;
        }
    }
    const float inv = (end > beg) ? 1.0f / (float)(end - beg) : 0.0f;
    __nv_bfloat162* ohi = reinterpret_cast<__nv_bfloat162*>(g_ahi) + (size_t)dst * P2;
    __nv_bfloat162* olo = reinterpret_cast<__nv_bfloat162*>(g_alo) + (size_t)dst * P2;
    #pragma unroll
    for (int j = 0; j < 3; ++j) {
        int p = t + j * 128;
        if (p >= P2) break;
        float vx = (p < F2) ? acc[j].x * inv : 0.f;
        float vy = (p < F2) ? acc[j].y * inv : 0.f;
        __nv_bfloat16 hx, lx, hy, ly;
        split_bf16(vx, hx, lx);
        split_bf16(vy, hy, ly);
        __nv_bfloat162 hp; hp.x = hx; hp.y = hy;
        __nv_bfloat162 lp; lp.x = lx; lp.y = ly;
        ohi[p] = hp;
        olo[p] = lp;
    }
}

// ---------------- tensor-core GEMM via mma.sync (HMMA, sm_80+ PTX) ----------
// h = relu([Xd | Hagg] @ [Ws; Wn] + b0), 3-term bf16 split into f32 acc.
// CTA tile 128x64; grid (86, 4); 8 warps = 4(M) x 2(N); warp tile 32x32.
// SMEM: double-buffered, per buf: Ah/Al 128x32, Bh/Bl 64x32, rows padded to 40.
#define BK        32
#define ROWP      40                       // padded row length (bf16)
#define A_TERM    (128 * ROWP * 2)         // 10240 B
#define B_TERM    (64 * ROWP * 2)          // 5120 B
#define BUF_SZ    (2 * A_TERM + 2 * B_TERM)  // 30720 B
#define GEMM_SMEM (2 * BUF_SZ)             // 61440 B
#define NCH       40                       // 2 phases x 20 K-chunks

#define CP16(dst, src, pred) \
    asm volatile("cp.async.cg.shared.global [%0], [%1], 16, %2;" \
                 :: "r"(dst), "l"(src), "r"(pred))
#define CP_COMMIT() asm volatile("cp.async.commit_group;" ::: "memory")
#define CP_WAIT(n)  asm volatile("cp.async.wait_group %0;" :: "n"(n) : "memory")

__device__ __forceinline__ uint32_t smem_u32(const void* p) {
    uint32_t a;
    asm("{ .reg .u64 t; cvta.to.shared.u64 t, %1; cvt.u32.u64 %0, t; }" : "=r"(a) : "l"(p));
    return a;
}

__device__ __forceinline__ void mma_bf16(float* d,
                                         const uint32_t* a, const uint32_t* b) {
    asm volatile(
        "mma.sync.aligned.m16n8k16.row.col.f32.bf16.bf16.f32 "
        "{%0,%1,%2,%3}, {%4,%5,%6,%7}, {%8,%9}, {%0,%1,%2,%3};"
        : "+f"(d[0]), "+f"(d[1]), "+f"(d[2]), "+f"(d[3])
        : "r"(a[0]), "r"(a[1]), "r"(a[2]), "r"(a[3]), "r"(b[0]), "r"(b[1]));
}

__global__ __launch_bounds__(256, 3)
void k_gemm_mma(const float* __restrict__ bias) {
    extern __shared__ char smem[];
    const uint32_t sb = smem_u32(smem);
    const int tid  = threadIdx.x;
    const int lane = tid & 31;
    const int wid  = tid >> 5;
    const int warpM = wid & 3;            // 0..3
    const int warpN = wid >> 2;           // 0..1
    const int g  = lane >> 2;             // 0..7
    const int tg = lane & 3;              // 0..3
    const int rowBase = blockIdx.x * 128;
    const int colBase = blockIdx.y * 64;

    // ---- async load issue for chunk c into buffer (c&1) ----
    auto issue = [&](int c) {
        const int ph = (c >= 20);
        const int kb = (c - ph * 20) * BK;
        const __nv_bfloat16* Ah = ph ? g_ahi : g_xhi;
        const __nv_bfloat16* Al = ph ? g_alo : g_xlo;
        const __nv_bfloat16* Bh = ph ? g_wnhi : g_wshi;
        const __nv_bfloat16* Bl = ph ? g_wnlo : g_wslo;
        const uint32_t bufb = sb + (uint32_t)(c & 1) * BUF_SZ;

        // A: 128 rows x 32k, hi+lo  (512 vec16 per term; 2 per thread)
        #pragma unroll
        for (int u = 0; u < 2; ++u) {
            int idx = tid + u * 256;          // 0..511
            int row = idx >> 2, v = idx & 3;
            int grow = rowBase + row;
            int pr = (grow < N_DST0) ? 16 : 0;
            size_t gb = ((size_t)grow * KPAD + kb + v * 8) * 2;  // bytes (guarded by pr)
            if (grow >= N_DST0) gb = 0;
            uint32_t so = bufb + (uint32_t)(row * (ROWP * 2) + v * 16);
            CP16(so,          (const char*)Ah + gb, pr);
            CP16(so + A_TERM, (const char*)Al + gb, pr);
        }
        // B: 64 rows x 32k, hi+lo (256 vec16 per term; 1 per thread)
        {
            int row = tid >> 2, v = tid & 3;
            size_t gb = ((size_t)(colBase + row) * KPAD + kb + v * 8) * 2;
            uint32_t so = bufb + (uint32_t)(2 * A_TERM + row * (ROWP * 2) + v * 16);
            CP16(so,          (const char*)Bh + gb, 16);
            CP16(so + B_TERM, (const char*)Bl + gb, 16);
        }
    };

    float acc[2][4][4] = {};   // [mtile][ntile][reg]

    issue(0);
    CP_COMMIT();

    for (int c = 0; c < NCH; ++c) {
        if (c + 1 < NCH) { issue(c + 1); CP_COMMIT(); CP_WAIT(1); }
        else             { CP_WAIT(0); }
        __syncthreads();

        const char* buf = smem + (c & 1) * BUF_SZ;
        const char* Ahs = buf;
        const char* Als = buf + A_TERM;
        const char* Bhs = buf + 2 * A_TERM;
        const char* Bls = buf + 2 * A_TERM + B_TERM;

        #pragma unroll
        for (int kk = 0; kk < BK; kk += 16) {
            const int kbyte = kk * 2 + tg * 4;

            // A-hi fragments (2 m-tiles)
            uint32_t aH[2][4];
            #pragma unroll
            for (int mt = 0; mt < 2; ++mt) {
                int r0 = warpM * 32 + mt * 16 + g;
                aH[mt][0] = *(const uint32_t*)(Ahs + r0 * (ROWP * 2) + kbyte);
                aH[mt][1] = *(const uint32_t*)(Ahs + (r0 + 8) * (ROWP * 2) + kbyte);
                aH[mt][2] = *(const uint32_t*)(Ahs + r0 * (ROWP * 2) + kbyte + 16);
                aH[mt][3] = *(const uint32_t*)(Ahs + (r0 + 8) * (ROWP * 2) + kbyte + 16);
            }
            // B-hi fragments (4 n-tiles)
            uint32_t bH[4][2];
            #pragma unroll
            for (int nt = 0; nt < 4; ++nt) {
                int r = warpN * 32 + nt * 8 + g;
                bH[nt][0] = *(const uint32_t*)(Bhs + r * (ROWP * 2) + kbyte);
                bH[nt][1] = *(const uint32_t*)(Bhs + r * (ROWP * 2) + kbyte + 16);
            }
            // term 1: Ah * Bh
            #pragma unroll
            for (int mt = 0; mt < 2; ++mt)
                #pragma unroll
                for (int nt = 0; nt < 4; ++nt)
                    mma_bf16(acc[mt][nt], aH[mt], bH[nt]);

            // term 2: Ah * Bl
            uint32_t bL[4][2];
            #pragma unroll
            for (int nt = 0; nt < 4; ++nt) {
                int r = warpN * 32 + nt * 8 + g;
                bL[nt][0] = *(const uint32_t*)(Bls + r * (ROWP * 2) + kbyte);
                bL[nt][1] = *(const uint32_t*)(Bls + r * (ROWP * 2) + kbyte + 16);
            }
            #pragma unroll
            for (int mt = 0; mt < 2; ++mt)
                #pragma unroll
                for (int nt = 0; nt < 4; ++nt)
                    mma_bf16(acc[mt][nt], aH[mt], bL[nt]);

            // term 3: Al * Bh
            uint32_t aL[2][4];
            #pragma unroll
            for (int mt = 0; mt < 2; ++mt) {
                int r0 = warpM * 32 + mt * 16 + g;
                aL[mt][0] = *(const uint32_t*)(Als + r0 * (ROWP * 2) + kbyte);
                aL[mt][1] = *(const uint32_t*)(Als + (r0 + 8) * (ROWP * 2) + kbyte);
                aL[mt][2] = *(const uint32_t*)(Als + r0 * (ROWP * 2) + kbyte + 16);
                aL[mt][3] = *(const uint32_t*)(Als + (r0 + 8) * (ROWP * 2) + kbyte + 16);
            }
            #pragma unroll
            for (int mt = 0; mt < 2; ++mt)
                #pragma unroll
                for (int nt = 0; nt < 4; ++nt)
                    mma_bf16(acc[mt][nt], aL[mt], bH[nt]);
        }
        __syncthreads();
    }

    // ---- epilogue: bias + relu, float2 stores ----
    float2 bv[4];
    #pragma unroll
    for (int nt = 0; nt < 4; ++nt) {
        int col = colBase + warpN * 32 + nt * 8 + tg * 2;
        bv[nt].x = __ldg(bias + col);
        bv[nt].y = __ldg(bias + col + 1);
    }
    #pragma unroll
    for (int mt = 0; mt < 2; ++mt) {
        #pragma unroll
        for (int half = 0; half < 2; ++half) {
            int row = rowBase + warpM * 32 + mt * 16 + g + half * 8;
            if (row >= N_DST0) continue;
            #pragma unroll
            for (int nt = 0; nt < 4; ++nt) {
                int col = colBase + warpN * 32 + nt * 8 + tg * 2;
                float2 o;
                o.x = fmaxf(acc[mt][nt][half * 2 + 0] + bv[nt].x, 0.f);
                o.y = fmaxf(acc[mt][nt][half * 2 + 1] + bv[nt].y, 0.f);
                *(float2*)(g_h + (size_t)row * HID + col) = o;
            }
        }
    }
}

// ---------------- layer-1 mean aggregation -----------------------------------
__global__ void k_agg1() {
    const int dst = blockIdx.x;
    const int beg = g_off1[dst];
    const int end = g_off1[dst + 1];
    const int t   = threadIdx.x;

    float acc = 0.f;
    for (int e = beg; e < end; ++e)
        acc += g_h[(size_t)g_src1[e] * HID + t];

    const float inv = (end > beg) ? 1.0f / (float)(end - beg) : 0.0f;
    g_hagg1[(size_t)dst * HID + t] = acc * inv;
}

// ---------------- output layer -------------------------------------------------
__global__ void k_out(const float* __restrict__ Ws1,
                      const float* __restrict__ Wn1,
                      const float* __restrict__ b1,
                      float* __restrict__ out) {
    __shared__ float hd[HID];
    __shared__ float ha[HID];
    const int dst = blockIdx.x;
    for (int i = threadIdx.x; i < HID; i += blockDim.x) {
        hd[i] = g_h[(size_t)dst * HID + i];
        ha[i] = g_hagg1[(size_t)dst * HID + i];
    }
    __syncthreads();
    const int c = threadIdx.x;
    if (c < NCLS) {
        float s = b1[c];
        #pragma unroll 4
        for (int k = 0; k < HID; ++k)
            s += hd[k] * Ws1[k * NCLS + c] + ha[k] * Wn1[k * NCLS + c];
        out[dst * NCLS + c] = s;
    }
}

// ---------------- launch --------------------------------------------------------
extern "C" void kernel_launch(void* const* d_in, const int* in_sizes, int n_in,
                              void* d_out, int out_size) {
    const float* x      = (const float*)d_in[0];
    const float* Wself0 = (const float*)d_in[1];
    const float* Wneigh0= (const float*)d_in[2];
    const float* b0     = (const float*)d_in[3];
    const float* Wself1 = (const float*)d_in[4];
    const float* Wneigh1= (const float*)d_in[5];
    const float* b1     = (const float*)d_in[6];
    const int*   e0_src = (const int*)d_in[7];
    const int*   e0_dst = (const int*)d_in[8];
    const int*   e1_src = (const int*)d_in[9];
    const int*   e1_dst = (const int*)d_in[10];
    float* out = (float*)d_out;

    static bool attr_set = false;
    if (!attr_set) {
        cudaFuncSetAttribute(k_gemm_mma, cudaFuncAttributeMaxDynamicSharedMemorySize, GEMM_SMEM);
        attr_set = true;
    }

    k_zero     <<<(N_DST0 + 255) / 256, 256>>>();
    k_count    <<<(N_E0 + 255) / 256, 256>>>(e0_dst, e1_dst);
    k_scan     <<<2, 1024>>>();
    k_scatter  <<<(N_E0 + 255) / 256, 256>>>(e0_src, e0_dst, e1_src, e1_dst);
    k_prep_w   <<<(2 * 256 * KPAD + 255) / 256, 256>>>(Wself0, Wneigh0);
    k_prep_x   <<<(N_DST0 * P2 + 255) / 256, 256>>>(x);
    k_agg0     <<<N_DST0, 128>>>(x);
    k_gemm_mma <<<dim3((N_DST0 + 127) / 128, 4), 256, GEMM_SMEM>>>(b0);
    k_agg1     <<<N_DST1, 256>>>();
    k_out      <<<N_DST1, 64>>>(Wself1, Wneigh1, b1, out);
}